// round 7
// baseline (speedup 1.0000x reference)
#include <cuda_runtime.h>
#include <cuda_bf16.h>
#include <cstdint>
#include <cstddef>

#define Bb 4
#define Nn 2048
#define Cc 1024
#define Hh 16
#define Dd 64

// Scratch (allocation-free rule: __device__ globals)
__device__ float g_qkv[(size_t)Bb * Nn * 3 * Cc];   // (B,N,3C)
__device__ float g_attn[(size_t)Bb * Nn * Cc];      // (B,N,C)

// ---------------------------------------------------------------------------
// helpers
// ---------------------------------------------------------------------------
__device__ __forceinline__ void bsplit2(float x0, float x1, uint32_t& h, uint32_t& l) {
    __nv_bfloat162 hv = __floats2bfloat162_rn(x0, x1);
    float2 hf = __bfloat1622float2(hv);
    __nv_bfloat162 lv = __floats2bfloat162_rn(x0 - hf.x, x1 - hf.y);
    h = *reinterpret_cast<uint32_t*>(&hv);
    l = *reinterpret_cast<uint32_t*>(&lv);
}

__device__ __forceinline__ void mmabf(float* c, const uint32_t* a, uint32_t b0, uint32_t b1) {
    asm volatile(
        "mma.sync.aligned.m16n8k16.row.col.f32.bf16.bf16.f32 "
        "{%0,%1,%2,%3},{%4,%5,%6,%7},{%8,%9},{%0,%1,%2,%3};"
        : "+f"(c[0]), "+f"(c[1]), "+f"(c[2]), "+f"(c[3])
        : "r"(a[0]), "r"(a[1]), "r"(a[2]), "r"(a[3]), "r"(b0), "r"(b1));
}

__device__ __forceinline__ void mma3(float* c,
                                     const uint32_t* ah, const uint32_t* al,
                                     uint32_t bh0, uint32_t bh1,
                                     uint32_t bl0, uint32_t bl1) {
    mmabf(c, al, bh0, bh1);
    mmabf(c, ah, bl0, bl1);
    mmabf(c, ah, bh0, bh1);
}

__device__ __forceinline__ uint32_t smem_u32(const void* p) {
    return (uint32_t)__cvta_generic_to_shared(p);
}

__device__ __forceinline__ void ldsm_x4(uint32_t* r, uint32_t addr) {
    asm volatile("ldmatrix.sync.aligned.m8n8.x4.shared.b16 {%0,%1,%2,%3}, [%4];"
                 : "=r"(r[0]), "=r"(r[1]), "=r"(r[2]), "=r"(r[3]) : "r"(addr));
}

__device__ __forceinline__ void ldsm_x4_t(uint32_t* r, uint32_t addr) {
    asm volatile("ldmatrix.sync.aligned.m8n8.x4.trans.shared.b16 {%0,%1,%2,%3}, [%4];"
                 : "=r"(r[0]), "=r"(r[1]), "=r"(r[2]), "=r"(r[3]) : "r"(addr));
}

// ---------------------------------------------------------------------------
// GEMM: C[M,N] = A[M,K] @ B[K,N] + bias[N]  (fp32 in/out, bf16x3, mma.sync)
// Block 128x128, K-tile 32, 256 threads, 8 warps (4 warp_m x 2 warp_n), 2 CTAs/SM.
// A: hi/lo packed-bf16x2 words along K (pitch 20 words) -> ldmatrix.x4.
// B: hi/lo k-major bf16 element array (pitch 136 bf16 = 68 words) -> ldmatrix.x4.trans.
// ---------------------------------------------------------------------------
constexpr int BM = 128, BN = 128, BK = 32;
constexpr int PAW = 20;                 // A word pitch
constexpr int PBH = 68;                 // B word pitch (136 bf16)
constexpr int AWSZ = BM * PAW;          // 2560 words
constexpr int BWSZ = BK * PBH;          // 2176 words
constexpr size_t GEMM_SMEM = (size_t)(2 * AWSZ + 2 * BWSZ) * 2 * 4;  // dbl-buf

__global__ __launch_bounds__(256, 2) void gemm_bias_bf16x3(
    const float* __restrict__ A, const float* __restrict__ Bm,
    const float* __restrict__ bias, float* __restrict__ Cm,
    int M, int N, int K)
{
    extern __shared__ uint32_t smw[];
    uint32_t* Ah = smw;                 // [2][AWSZ]
    uint32_t* Al = Ah + 2 * AWSZ;
    uint32_t* Bh = Al + 2 * AWSZ;       // [2][BWSZ]
    uint32_t* Bl = Bh + 2 * BWSZ;

    const uint32_t AhB = smem_u32(Ah);
    const uint32_t AlB = smem_u32(Al);
    const uint32_t BhB = smem_u32(Bh);
    const uint32_t BlB = smem_u32(Bl);

    const int tid = threadIdx.x;
    const int m0 = blockIdx.y * BM;
    const int n0 = blockIdx.x * BN;

    const int warp = tid >> 5;
    const int lane = tid & 31;
    const int warp_m = warp >> 1;   // 0..3
    const int warp_n = warp & 1;    // 0..1

    // ldmatrix per-lane offsets
    const int arow = (lane & 7) + ((lane >> 3) & 1) * 8;  // 0..15
    const int asel = (lane >> 4) * 16;                    // bytes (4 words)
    const int bn8 = (lane >> 4) * 8;                      // n offset (bf16)

    float acc[2][8][4] = {};
    const int KT = K / BK;

    float2 a_reg[8];
    float4 b_reg[4];

    auto ldg_stage = [&](int kt) {
        const int k0 = kt * BK;
        #pragma unroll
        for (int i = 0; i < 8; i++) {
            int idx = i * 256 + tid;            // 2048 items: r x w
            int r = idx >> 4, w = idx & 15;
            a_reg[i] = *(const float2*)&A[(size_t)(m0 + r) * K + k0 + 2 * w];
        }
        #pragma unroll
        for (int i = 0; i < 4; i++) {
            int c = i * 256 + tid;              // 1024 float4: k x f4
            int k = c >> 5, f4 = c & 31;
            b_reg[i] = *(const float4*)&Bm[(size_t)(k0 + k) * N + n0 + 4 * f4];
        }
    };

    auto sts_stage = [&](int s) {
        uint32_t* ah = Ah + s * AWSZ;
        uint32_t* al = Al + s * AWSZ;
        uint32_t* bhp = Bh + s * BWSZ;
        uint32_t* blp = Bl + s * BWSZ;
        #pragma unroll
        for (int i = 0; i < 8; i++) {
            int idx = i * 256 + tid;
            int r = idx >> 4, w = idx & 15;
            bsplit2(a_reg[i].x, a_reg[i].y, ah[r * PAW + w], al[r * PAW + w]);
        }
        #pragma unroll
        for (int i = 0; i < 4; i++) {
            int c = i * 256 + tid;
            int k = c >> 5, f4 = c & 31;
            uint32_t h0, l0, h1, l1;
            bsplit2(b_reg[i].x, b_reg[i].y, h0, l0);
            bsplit2(b_reg[i].z, b_reg[i].w, h1, l1);
            *(uint2*)&bhp[k * PBH + 2 * f4] = make_uint2(h0, h1);
            *(uint2*)&blp[k * PBH + 2 * f4] = make_uint2(l0, l1);
        }
    };

    auto compute_slab = [&](int s, int ks) {
        const uint32_t aoff = (uint32_t)(s * AWSZ * 4);
        const uint32_t boff = (uint32_t)(s * BWSZ * 4);
        uint32_t afh[2][4], afl[2][4];
        #pragma unroll
        for (int mt = 0; mt < 2; mt++) {
            uint32_t abyte = (uint32_t)((warp_m * 32 + mt * 16 + arow) * (PAW * 4)
                                        + ks * 32 + asel);
            ldsm_x4(afh[mt], AhB + aoff + abyte);
            ldsm_x4(afl[mt], AlB + aoff + abyte);
        }
        #pragma unroll
        for (int np = 0; np < 4; np++) {
            uint32_t bbyte = (uint32_t)((16 * ks + arow) * (PBH * 4)
                                        + (64 * warp_n + 16 * np + bn8) * 2);
            uint32_t bh[4], bl[4];
            ldsm_x4_t(bh, BhB + boff + bbyte);
            ldsm_x4_t(bl, BlB + boff + bbyte);
            mma3(acc[0][2 * np],     afh[0], afl[0], bh[0], bh[1], bl[0], bl[1]);
            mma3(acc[1][2 * np],     afh[1], afl[1], bh[0], bh[1], bl[0], bl[1]);
            mma3(acc[0][2 * np + 1], afh[0], afl[0], bh[2], bh[3], bl[2], bl[3]);
            mma3(acc[1][2 * np + 1], afh[1], afl[1], bh[2], bh[3], bl[2], bl[3]);
        }
    };

    ldg_stage(0);
    sts_stage(0);
    __syncthreads();

    for (int kt = 0; kt < KT; kt++) {
        const int s = kt & 1;
        if (kt + 1 < KT) ldg_stage(kt + 1);
        compute_slab(s, 0);                       // covers LDG latency
        if (kt + 1 < KT) sts_stage(s ^ 1);        // writes other stage
        compute_slab(s, 1);
        __syncthreads();
    }

    // epilogue: + bias, fp32 out
    const int g = lane >> 2;
    const int t = lane & 3;
    #pragma unroll
    for (int mt = 0; mt < 2; mt++) {
        int r0 = m0 + warp_m * 32 + mt * 16 + g;
        #pragma unroll
        for (int nt = 0; nt < 8; nt++) {
            int c = n0 + warp_n * 64 + nt * 8 + 2 * t;
            float bz0 = bias[c], bz1 = bias[c + 1];
            float2 v0 = make_float2(acc[mt][nt][0] + bz0, acc[mt][nt][1] + bz1);
            float2 v1 = make_float2(acc[mt][nt][2] + bz0, acc[mt][nt][3] + bz1);
            *(float2*)&Cm[(size_t)r0 * N + c] = v0;
            *(float2*)&Cm[(size_t)(r0 + 8) * N + c] = v1;
        }
    }
}

// ---------------------------------------------------------------------------
// Flash attention (no sqrt(d) scaling). bf16x3 mma. 2 CTAs/SM.
// Grid: (B*H, N/128). 256 threads = 8 warps, warp owns 16 query rows.
// Q: words along d (pitch 36), frags via ldmatrix.x4 (A pattern).
// K: rows=key, words along d (pitch 36), frags via ldmatrix.x4 (B pattern).
// V: n-major — rows=d, words=key-pairs (pitch 36), frags via ldmatrix.x4.
// P never touches smem (S C-frag == PV A-frag identity).
// ---------------------------------------------------------------------------
constexpr int PW = 36;                 // word pitch (144 B) for Q/K/V
constexpr int QW = 128 * PW;
constexpr int KW = 64 * PW;
constexpr int VW = 64 * PW;
constexpr size_t FL_SMEM = (size_t)(2 * QW + 2 * KW + 2 * VW) * 4;

__global__ __launch_bounds__(256, 2) void flash_attn(
    const float* __restrict__ qkv, float* __restrict__ attn_out)
{
    extern __shared__ uint32_t smw[];
    uint32_t* Qh = smw;
    uint32_t* Ql = Qh + QW;
    uint32_t* Kh = Ql + QW;
    uint32_t* Kl = Kh + KW;
    uint32_t* Vh = Kl + KW;
    uint32_t* Vl = Vh + VW;

    const uint32_t QhB = smem_u32(Qh);
    const uint32_t QlB = smem_u32(Ql);
    const uint32_t KhB = smem_u32(Kh);
    const uint32_t KlB = smem_u32(Kl);
    const uint32_t VhB = smem_u32(Vh);
    const uint32_t VlB = smem_u32(Vl);

    const int tid = threadIdx.x;
    const int bh = blockIdx.x;
    const int b = bh / Hh, h = bh % Hh;
    const int q0 = blockIdx.y * 128;

    const int warp = tid >> 5;
    const int lane = tid & 31;
    const int g = lane >> 2;
    const int t = lane & 3;

    // ldmatrix per-lane offsets
    const int arow = (lane & 7) + ((lane >> 3) & 1) * 8;  // A pattern row
    const int asel = (lane >> 4) * 16;                    // A pattern byte sel
    const int brow = (lane & 7) + (lane >> 4) * 8;        // B pattern row
    const int bsel = ((lane >> 3) & 1) * 16;              // B pattern byte sel

    const size_t row_stride = (size_t)3 * Cc;
    const size_t base = (size_t)(b * Nn) * row_stride;
    const int qoff = h * Dd;
    const int koff = Cc + h * Dd;
    const int voff = 2 * Cc + h * Dd;

    // load + split Q tile (128 x 64) once
    #pragma unroll
    for (int i = 0; i < 16; i++) {
        int idx = i * 256 + tid;
        int r = idx >> 5, w = idx & 31;
        float2 v = *(const float2*)&qkv[base + (size_t)(q0 + r) * row_stride + qoff + 2 * w];
        bsplit2(v.x, v.y, Qh[r * PW + w], Ql[r * PW + w]);
    }

    float m_run[2] = { -1e30f, -1e30f };
    float l_run[2] = { 0.f, 0.f };
    float oacc[8][4] = {};

    const int rq = warp * 16;

    for (int kt = 0; kt < Nn / 64; kt++) {
        const int k0 = kt * 64;
        __syncthreads();   // previous iter's K/V reads done; Q ready (iter 0)

        // load + split K (64x64)
        #pragma unroll
        for (int i = 0; i < 8; i++) {
            int idx = i * 256 + tid;
            int r = idx >> 5, w = idx & 31;
            float2 kv = *(const float2*)&qkv[base + (size_t)(k0 + r) * row_stride + koff + 2 * w];
            bsplit2(kv.x, kv.y, Kh[r * PW + w], Kl[r * PW + w]);
        }
        // load + split V, store n-major: row=d, word=key-pair
        #pragma unroll
        for (int i = 0; i < 4; i++) {
            int idx = i * 256 + tid;
            int k2 = idx >> 5, n2 = idx & 31;
            float2 v0 = *(const float2*)&qkv[base + (size_t)(k0 + 2 * k2) * row_stride + voff + 2 * n2];
            float2 v1 = *(const float2*)&qkv[base + (size_t)(k0 + 2 * k2 + 1) * row_stride + voff + 2 * n2];
            uint32_t h0, l0, h1, l1;
            bsplit2(v0.x, v1.x, h0, l0);   // d = 2*n2
            bsplit2(v0.y, v1.y, h1, l1);   // d = 2*n2+1
            Vh[(2 * n2) * PW + k2] = h0;
            Vh[(2 * n2 + 1) * PW + k2] = h1;
            Vl[(2 * n2) * PW + k2] = l0;
            Vl[(2 * n2 + 1) * PW + k2] = l1;
        }
        __syncthreads();

        // S = Q K^T  (16 x 64 per warp), bf16x3; k = d (4 slabs of 16)
        float s[8][4] = {};
        #pragma unroll
        for (int ks = 0; ks < 4; ks++) {
            uint32_t qbyte = (uint32_t)((rq + arow) * (PW * 4) + ks * 32 + asel);
            uint32_t ah[4], al[4];
            ldsm_x4(ah, QhB + qbyte);
            ldsm_x4(al, QlB + qbyte);
            #pragma unroll
            for (int np = 0; np < 4; np++) {
                uint32_t kbyte = (uint32_t)((16 * np + brow) * (PW * 4) + ks * 32 + bsel);
                uint32_t kh[4], kl[4];
                ldsm_x4(kh, KhB + kbyte);
                ldsm_x4(kl, KlB + kbyte);
                mma3(s[2 * np],     ah, al, kh[0], kh[1], kl[0], kl[1]);
                mma3(s[2 * np + 1], ah, al, kh[2], kh[3], kl[2], kl[3]);
            }
        }

        // online softmax per row (2 rows per thread: g, g+8)
        #pragma unroll
        for (int rr = 0; rr < 2; rr++) {
            int j0 = rr * 2;
            float mx = -1e30f;
            #pragma unroll
            for (int nt = 0; nt < 8; nt++)
                mx = fmaxf(mx, fmaxf(s[nt][j0], s[nt][j0 + 1]));
            mx = fmaxf(mx, __shfl_xor_sync(0xffffffffu, mx, 1));
            mx = fmaxf(mx, __shfl_xor_sync(0xffffffffu, mx, 2));
            float newm = fmaxf(m_run[rr], mx);
            float scale = __expf(m_run[rr] - newm);
            m_run[rr] = newm;
            float rsum = 0.f;
            #pragma unroll
            for (int nt = 0; nt < 8; nt++) {
                float p0 = __expf(s[nt][j0] - newm);
                float p1 = __expf(s[nt][j0 + 1] - newm);
                s[nt][j0] = p0; s[nt][j0 + 1] = p1;
                rsum += p0 + p1;
            }
            rsum += __shfl_xor_sync(0xffffffffu, rsum, 1);
            rsum += __shfl_xor_sync(0xffffffffu, rsum, 2);
            l_run[rr] = l_run[rr] * scale + rsum;
            #pragma unroll
            for (int nt = 0; nt < 8; nt++) {
                oacc[nt][j0] *= scale;
                oacc[nt][j0 + 1] *= scale;
            }
        }

        // O += P V  (k = key 64, 4 slabs), bf16x3.
        // P a-frags straight from the S C-frags (layout identity).
        #pragma unroll
        for (int ks = 0; ks < 4; ks++) {
            uint32_t ah[4], al[4];
            bsplit2(s[2 * ks][0],     s[2 * ks][1],     ah[0], al[0]);
            bsplit2(s[2 * ks][2],     s[2 * ks][3],     ah[1], al[1]);
            bsplit2(s[2 * ks + 1][0], s[2 * ks + 1][1], ah[2], al[2]);
            bsplit2(s[2 * ks + 1][2], s[2 * ks + 1][3], ah[3], al[3]);
            #pragma unroll
            for (int np = 0; np < 4; np++) {
                uint32_t vbyte = (uint32_t)((16 * np + brow) * (PW * 4) + ks * 32 + bsel);
                uint32_t vh[4], vl[4];
                ldsm_x4(vh, VhB + vbyte);
                ldsm_x4(vl, VlB + vbyte);
                mma3(oacc[2 * np],     ah, al, vh[0], vh[1], vl[0], vl[1]);
                mma3(oacc[2 * np + 1], ah, al, vh[2], vh[3], vl[2], vl[3]);
            }
        }
    }

    // normalize + write out: attn_out[(b*N + n) * C + h*D + d]
    float inv0 = 1.f / l_run[0];
    float inv1 = 1.f / l_run[1];
    size_t orow0 = (size_t)(b * Nn + q0 + rq + g) * Cc + h * Dd;
    size_t orow1 = (size_t)(b * Nn + q0 + rq + 8 + g) * Cc + h * Dd;
    #pragma unroll
    for (int nt = 0; nt < 8; nt++) {
        int c = nt * 8 + 2 * t;
        *(float2*)&attn_out[orow0 + c] = make_float2(oacc[nt][0] * inv0, oacc[nt][1] * inv0);
        *(float2*)&attn_out[orow1 + c] = make_float2(oacc[nt][2] * inv1, oacc[nt][3] * inv1);
    }
}

// ---------------------------------------------------------------------------
// launch
// ---------------------------------------------------------------------------
extern "C" void kernel_launch(void* const* d_in, const int* in_sizes, int n_in,
                              void* d_out, int out_size)
{
    const float* x     = (const float*)d_in[0];
    const float* w_in  = (const float*)d_in[1];
    const float* b_in  = (const float*)d_in[2];
    const float* w_out = (const float*)d_in[3];
    const float* b_out = (const float*)d_in[4];
    float* out = (float*)d_out;

    float* qkv;
    float* attn;
    cudaGetSymbolAddress((void**)&qkv, g_qkv);
    cudaGetSymbolAddress((void**)&attn, g_attn);

    cudaFuncSetAttribute(gemm_bias_bf16x3, cudaFuncAttributeMaxDynamicSharedMemorySize,
                         (int)GEMM_SMEM);
    cudaFuncSetAttribute(flash_attn, cudaFuncAttributeMaxDynamicSharedMemorySize,
                         (int)FL_SMEM);

    const int M = Bb * Nn;  // 8192

    // 1) qkv = x @ w_in + b_in     (8192 x 3072 x 1024)
    gemm_bias_bf16x3<<<dim3(3 * Cc / BN, M / BM), 256, GEMM_SMEM>>>(
        x, w_in, b_in, qkv, M, 3 * Cc, Cc);

    // 2) flash attention -> attn (B,N,C)
    flash_attn<<<dim3(Bb * Hh, Nn / 128), 256, FL_SMEM>>>(qkv, attn);

    // 3) out = attn @ w_out + b_out   (8192 x 1024 x 1024)
    gemm_bias_bf16x3<<<dim3(Cc / BN, M / BM), 256, GEMM_SMEM>>>(
        attn, w_out, b_out, out, M, Cc, Cc);
}

// round 8
// speedup vs baseline: 1.0309x; 1.0309x over previous
#include <cuda_runtime.h>
#include <cuda_bf16.h>
#include <cstdint>
#include <cstddef>

#define Bb 4
#define Nn 2048
#define Cc 1024
#define Hh 16
#define Dd 64

// Scratch (allocation-free rule: __device__ globals)
__device__ float g_qkv[(size_t)Bb * Nn * 3 * Cc];   // (B,N,3C)
__device__ float g_attn[(size_t)Bb * Nn * Cc];      // (B,N,C)

// ---------------------------------------------------------------------------
// helpers
// ---------------------------------------------------------------------------
__device__ __forceinline__ void bsplit2(float x0, float x1, uint32_t& h, uint32_t& l) {
    __nv_bfloat162 hv = __floats2bfloat162_rn(x0, x1);
    float2 hf = __bfloat1622float2(hv);
    __nv_bfloat162 lv = __floats2bfloat162_rn(x0 - hf.x, x1 - hf.y);
    h = *reinterpret_cast<uint32_t*>(&hv);
    l = *reinterpret_cast<uint32_t*>(&lv);
}

__device__ __forceinline__ void mmabf(float* c, const uint32_t* a, uint32_t b0, uint32_t b1) {
    asm volatile(
        "mma.sync.aligned.m16n8k16.row.col.f32.bf16.bf16.f32 "
        "{%0,%1,%2,%3},{%4,%5,%6,%7},{%8,%9},{%0,%1,%2,%3};"
        : "+f"(c[0]), "+f"(c[1]), "+f"(c[2]), "+f"(c[3])
        : "r"(a[0]), "r"(a[1]), "r"(a[2]), "r"(a[3]), "r"(b0), "r"(b1));
}

__device__ __forceinline__ void mma3(float* c,
                                     const uint32_t* ah, const uint32_t* al,
                                     uint32_t bh0, uint32_t bh1,
                                     uint32_t bl0, uint32_t bl1) {
    mmabf(c, al, bh0, bh1);
    mmabf(c, ah, bl0, bl1);
    mmabf(c, ah, bh0, bh1);
}

__device__ __forceinline__ uint32_t smem_u32(const void* p) {
    return (uint32_t)__cvta_generic_to_shared(p);
}

__device__ __forceinline__ void ldsm_x4(uint32_t* r, uint32_t addr) {
    asm volatile("ldmatrix.sync.aligned.m8n8.x4.shared.b16 {%0,%1,%2,%3}, [%4];"
                 : "=r"(r[0]), "=r"(r[1]), "=r"(r[2]), "=r"(r[3]) : "r"(addr));
}

__device__ __forceinline__ void ldsm_x4_t(uint32_t* r, uint32_t addr) {
    asm volatile("ldmatrix.sync.aligned.m8n8.x4.trans.shared.b16 {%0,%1,%2,%3}, [%4];"
                 : "=r"(r[0]), "=r"(r[1]), "=r"(r[2]), "=r"(r[3]) : "r"(addr));
}

// ---------------------------------------------------------------------------
// GEMM: C[M,N] = A[M,K] @ B[K,N] + bias[N]  (fp32 in/out, bf16x3, mma.sync)
// Block 128x128, K-tile 32, 256 threads, 8 warps (4 warp_m x 2 warp_n), 2 CTAs/SM.
// Software pipeline: LDG issued 1.5 ktiles before STS consumption.
// ---------------------------------------------------------------------------
constexpr int BM = 128, BN = 128, BK = 32;
constexpr int PAW = 20;                 // A word pitch
constexpr int PBH = 68;                 // B word pitch (136 bf16)
constexpr int AWSZ = BM * PAW;          // 2560 words
constexpr int BWSZ = BK * PBH;          // 2176 words
constexpr size_t GEMM_SMEM = (size_t)(2 * AWSZ + 2 * BWSZ) * 2 * 4;  // dbl-buf

__global__ __launch_bounds__(256, 2) void gemm_bias_bf16x3(
    const float* __restrict__ A, const float* __restrict__ Bm,
    const float* __restrict__ bias, float* __restrict__ Cm,
    int M, int N, int K)
{
    extern __shared__ uint32_t smw[];
    uint32_t* Ah = smw;                 // [2][AWSZ]
    uint32_t* Al = Ah + 2 * AWSZ;
    uint32_t* Bh = Al + 2 * AWSZ;       // [2][BWSZ]
    uint32_t* Bl = Bh + 2 * BWSZ;

    const uint32_t AhB = smem_u32(Ah);
    const uint32_t AlB = smem_u32(Al);
    const uint32_t BhB = smem_u32(Bh);
    const uint32_t BlB = smem_u32(Bl);

    const int tid = threadIdx.x;
    const int m0 = blockIdx.y * BM;
    const int n0 = blockIdx.x * BN;

    const int warp = tid >> 5;
    const int lane = tid & 31;
    const int warp_m = warp >> 1;   // 0..3
    const int warp_n = warp & 1;    // 0..1

    // ldmatrix per-lane offsets
    const int arow = (lane & 7) + ((lane >> 3) & 1) * 8;  // 0..15
    const int asel = (lane >> 4) * 16;                    // bytes (4 words)
    const int bn8 = (lane >> 4) * 8;                      // n offset (bf16)

    float acc[2][8][4] = {};
    const int KT = K / BK;

    float2 a_reg[8];
    float4 b_reg[4];

    auto ldg_stage = [&](int kt) {
        const int k0 = kt * BK;
        #pragma unroll
        for (int i = 0; i < 8; i++) {
            int idx = i * 256 + tid;            // 2048 items: r x w
            int r = idx >> 4, w = idx & 15;
            a_reg[i] = *(const float2*)&A[(size_t)(m0 + r) * K + k0 + 2 * w];
        }
        #pragma unroll
        for (int i = 0; i < 4; i++) {
            int c = i * 256 + tid;              // 1024 float4: k x f4
            int k = c >> 5, f4 = c & 31;
            b_reg[i] = *(const float4*)&Bm[(size_t)(k0 + k) * N + n0 + 4 * f4];
        }
    };

    auto sts_stage = [&](int s) {
        uint32_t* ah = Ah + s * AWSZ;
        uint32_t* al = Al + s * AWSZ;
        uint32_t* bhp = Bh + s * BWSZ;
        uint32_t* blp = Bl + s * BWSZ;
        #pragma unroll
        for (int i = 0; i < 8; i++) {
            int idx = i * 256 + tid;
            int r = idx >> 4, w = idx & 15;
            bsplit2(a_reg[i].x, a_reg[i].y, ah[r * PAW + w], al[r * PAW + w]);
        }
        #pragma unroll
        for (int i = 0; i < 4; i++) {
            int c = i * 256 + tid;
            int k = c >> 5, f4 = c & 31;
            uint32_t h0, l0, h1, l1;
            bsplit2(b_reg[i].x, b_reg[i].y, h0, l0);
            bsplit2(b_reg[i].z, b_reg[i].w, h1, l1);
            *(uint2*)&bhp[k * PBH + 2 * f4] = make_uint2(h0, h1);
            *(uint2*)&blp[k * PBH + 2 * f4] = make_uint2(l0, l1);
        }
    };

    auto compute_slab = [&](int s, int ks) {
        const uint32_t aoff = (uint32_t)(s * AWSZ * 4);
        const uint32_t boff = (uint32_t)(s * BWSZ * 4);
        uint32_t afh[2][4], afl[2][4];
        #pragma unroll
        for (int mt = 0; mt < 2; mt++) {
            uint32_t abyte = (uint32_t)((warp_m * 32 + mt * 16 + arow) * (PAW * 4)
                                        + ks * 32 + asel);
            ldsm_x4(afh[mt], AhB + aoff + abyte);
            ldsm_x4(afl[mt], AlB + aoff + abyte);
        }
        #pragma unroll
        for (int np = 0; np < 4; np++) {
            uint32_t bbyte = (uint32_t)((16 * ks + arow) * (PBH * 4)
                                        + (64 * warp_n + 16 * np + bn8) * 2);
            uint32_t bh[4], bl[4];
            ldsm_x4_t(bh, BhB + boff + bbyte);
            ldsm_x4_t(bl, BlB + boff + bbyte);
            mma3(acc[0][2 * np],     afh[0], afl[0], bh[0], bh[1], bl[0], bl[1]);
            mma3(acc[1][2 * np],     afh[1], afl[1], bh[0], bh[1], bl[0], bl[1]);
            mma3(acc[0][2 * np + 1], afh[0], afl[0], bh[2], bh[3], bl[2], bl[3]);
            mma3(acc[1][2 * np + 1], afh[1], afl[1], bh[2], bh[3], bl[2], bl[3]);
        }
    };

    // Prologue: stage 0 in smem; ktile 1 in regs.
    ldg_stage(0);
    sts_stage(0);
    if (KT > 1) ldg_stage(1);
    __syncthreads();

    for (int kt = 0; kt < KT; kt++) {
        const int s = kt & 1;
        compute_slab(s, 0);
        if (kt + 1 < KT) sts_stage(s ^ 1);        // from regs (ktile kt+1)
        if (kt + 2 < KT) ldg_stage(kt + 2);       // ~1 ktile of latency cover
        compute_slab(s, 1);
        __syncthreads();
    }

    // epilogue: + bias, fp32 out
    const int g = lane >> 2;
    const int t = lane & 3;
    #pragma unroll
    for (int mt = 0; mt < 2; mt++) {
        int r0 = m0 + warp_m * 32 + mt * 16 + g;
        #pragma unroll
        for (int nt = 0; nt < 8; nt++) {
            int c = n0 + warp_n * 64 + nt * 8 + 2 * t;
            float bz0 = bias[c], bz1 = bias[c + 1];
            float2 v0 = make_float2(acc[mt][nt][0] + bz0, acc[mt][nt][1] + bz1);
            float2 v1 = make_float2(acc[mt][nt][2] + bz0, acc[mt][nt][3] + bz1);
            *(float2*)&Cm[(size_t)r0 * N + c] = v0;
            *(float2*)&Cm[(size_t)(r0 + 8) * N + c] = v1;
        }
    }
}

// ---------------------------------------------------------------------------
// Flash attention (no sqrt(d) scaling). bf16x3 mma. 2 CTAs/SM.
// Grid: (B*H, N/128). 256 threads = 8 warps, warp owns 16 query rows.
// K/V for iter kt+1 prefetched into registers during iter kt's compute.
// P never touches smem (S C-frag == PV A-frag identity).
// ---------------------------------------------------------------------------
constexpr int PW = 36;                 // word pitch (144 B) for Q/K/V
constexpr int QW = 128 * PW;
constexpr int KW = 64 * PW;
constexpr int VW = 64 * PW;
constexpr size_t FL_SMEM = (size_t)(2 * QW + 2 * KW + 2 * VW) * 4;

__global__ __launch_bounds__(256, 2) void flash_attn(
    const float* __restrict__ qkv, float* __restrict__ attn_out)
{
    extern __shared__ uint32_t smw[];
    uint32_t* Qh = smw;
    uint32_t* Ql = Qh + QW;
    uint32_t* Kh = Ql + QW;
    uint32_t* Kl = Kh + KW;
    uint32_t* Vh = Kl + KW;
    uint32_t* Vl = Vh + VW;

    const uint32_t QhB = smem_u32(Qh);
    const uint32_t QlB = smem_u32(Ql);
    const uint32_t KhB = smem_u32(Kh);
    const uint32_t KlB = smem_u32(Kl);
    const uint32_t VhB = smem_u32(Vh);
    const uint32_t VlB = smem_u32(Vl);

    const int tid = threadIdx.x;
    const int bh = blockIdx.x;
    const int b = bh / Hh, h = bh % Hh;
    const int q0 = blockIdx.y * 128;

    const int warp = tid >> 5;
    const int lane = tid & 31;
    const int g = lane >> 2;
    const int t = lane & 3;

    // ldmatrix per-lane offsets
    const int arow = (lane & 7) + ((lane >> 3) & 1) * 8;  // A pattern row
    const int asel = (lane >> 4) * 16;                    // A pattern byte sel
    const int brow = (lane & 7) + (lane >> 4) * 8;        // B pattern row
    const int bsel = ((lane >> 3) & 1) * 16;              // B pattern byte sel

    const size_t row_stride = (size_t)3 * Cc;
    const size_t base = (size_t)(b * Nn) * row_stride;
    const int qoff = h * Dd;
    const int koff = Cc + h * Dd;
    const int voff = 2 * Cc + h * Dd;

    float2 k_reg[8];
    float2 v_reg[8];

    auto ldg_kv = [&](int kt) {
        const int k0 = kt * 64;
        #pragma unroll
        for (int i = 0; i < 8; i++) {
            int idx = i * 256 + tid;
            int r = idx >> 5, w = idx & 31;
            k_reg[i] = *(const float2*)&qkv[base + (size_t)(k0 + r) * row_stride + koff + 2 * w];
        }
        #pragma unroll
        for (int i = 0; i < 4; i++) {
            int idx = i * 256 + tid;
            int k2 = idx >> 5, n2 = idx & 31;
            v_reg[2 * i]     = *(const float2*)&qkv[base + (size_t)(k0 + 2 * k2) * row_stride + voff + 2 * n2];
            v_reg[2 * i + 1] = *(const float2*)&qkv[base + (size_t)(k0 + 2 * k2 + 1) * row_stride + voff + 2 * n2];
        }
    };

    auto sts_kv = [&]() {
        #pragma unroll
        for (int i = 0; i < 8; i++) {
            int idx = i * 256 + tid;
            int r = idx >> 5, w = idx & 31;
            bsplit2(k_reg[i].x, k_reg[i].y, Kh[r * PW + w], Kl[r * PW + w]);
        }
        #pragma unroll
        for (int i = 0; i < 4; i++) {
            int idx = i * 256 + tid;
            int k2 = idx >> 5, n2 = idx & 31;
            float2 v0 = v_reg[2 * i], v1 = v_reg[2 * i + 1];
            uint32_t h0, l0, h1, l1;
            bsplit2(v0.x, v1.x, h0, l0);   // d = 2*n2
            bsplit2(v0.y, v1.y, h1, l1);   // d = 2*n2+1
            Vh[(2 * n2) * PW + k2] = h0;
            Vh[(2 * n2 + 1) * PW + k2] = h1;
            Vl[(2 * n2) * PW + k2] = l0;
            Vl[(2 * n2 + 1) * PW + k2] = l1;
        }
    };

    // load + split Q tile (128 x 64) once
    #pragma unroll
    for (int i = 0; i < 16; i++) {
        int idx = i * 256 + tid;
        int r = idx >> 5, w = idx & 31;
        float2 v = *(const float2*)&qkv[base + (size_t)(q0 + r) * row_stride + qoff + 2 * w];
        bsplit2(v.x, v.y, Qh[r * PW + w], Ql[r * PW + w]);
    }

    float m_run[2] = { -1e30f, -1e30f };
    float l_run[2] = { 0.f, 0.f };
    float oacc[8][4] = {};

    const int rq = warp * 16;

    ldg_kv(0);   // prologue prefetch

    for (int kt = 0; kt < Nn / 64; kt++) {
        sts_kv();            // tile kt from regs
        __syncthreads();     // K/V (and Q on iter 0) visible
        if (kt + 1 < Nn / 64) ldg_kv(kt + 1);   // covered by full compute phase

        // S = Q K^T  (16 x 64 per warp), bf16x3; k = d (4 slabs of 16)
        float s[8][4] = {};
        #pragma unroll
        for (int ks = 0; ks < 4; ks++) {
            uint32_t qbyte = (uint32_t)((rq + arow) * (PW * 4) + ks * 32 + asel);
            uint32_t ah[4], al[4];
            ldsm_x4(ah, QhB + qbyte);
            ldsm_x4(al, QlB + qbyte);
            #pragma unroll
            for (int np = 0; np < 4; np++) {
                uint32_t kbyte = (uint32_t)((16 * np + brow) * (PW * 4) + ks * 32 + bsel);
                uint32_t kh[4], kl[4];
                ldsm_x4(kh, KhB + kbyte);
                ldsm_x4(kl, KlB + kbyte);
                mma3(s[2 * np],     ah, al, kh[0], kh[1], kl[0], kl[1]);
                mma3(s[2 * np + 1], ah, al, kh[2], kh[3], kl[2], kl[3]);
            }
        }

        // online softmax per row (2 rows per thread: g, g+8)
        #pragma unroll
        for (int rr = 0; rr < 2; rr++) {
            int j0 = rr * 2;
            float mx = -1e30f;
            #pragma unroll
            for (int nt = 0; nt < 8; nt++)
                mx = fmaxf(mx, fmaxf(s[nt][j0], s[nt][j0 + 1]));
            mx = fmaxf(mx, __shfl_xor_sync(0xffffffffu, mx, 1));
            mx = fmaxf(mx, __shfl_xor_sync(0xffffffffu, mx, 2));
            float newm = fmaxf(m_run[rr], mx);
            float scale = __expf(m_run[rr] - newm);
            m_run[rr] = newm;
            float rsum = 0.f;
            #pragma unroll
            for (int nt = 0; nt < 8; nt++) {
                float p0 = __expf(s[nt][j0] - newm);
                float p1 = __expf(s[nt][j0 + 1] - newm);
                s[nt][j0] = p0; s[nt][j0 + 1] = p1;
                rsum += p0 + p1;
            }
            rsum += __shfl_xor_sync(0xffffffffu, rsum, 1);
            rsum += __shfl_xor_sync(0xffffffffu, rsum, 2);
            l_run[rr] = l_run[rr] * scale + rsum;
            #pragma unroll
            for (int nt = 0; nt < 8; nt++) {
                oacc[nt][j0] *= scale;
                oacc[nt][j0 + 1] *= scale;
            }
        }

        // O += P V  (k = key 64, 4 slabs), bf16x3.
        #pragma unroll
        for (int ks = 0; ks < 4; ks++) {
            uint32_t ah[4], al[4];
            bsplit2(s[2 * ks][0],     s[2 * ks][1],     ah[0], al[0]);
            bsplit2(s[2 * ks][2],     s[2 * ks][3],     ah[1], al[1]);
            bsplit2(s[2 * ks + 1][0], s[2 * ks + 1][1], ah[2], al[2]);
            bsplit2(s[2 * ks + 1][2], s[2 * ks + 1][3], ah[3], al[3]);
            #pragma unroll
            for (int np = 0; np < 4; np++) {
                uint32_t vbyte = (uint32_t)((16 * np + brow) * (PW * 4) + ks * 32 + bsel);
                uint32_t vh[4], vl[4];
                ldsm_x4(vh, VhB + vbyte);
                ldsm_x4(vl, VlB + vbyte);
                mma3(oacc[2 * np],     ah, al, vh[0], vh[1], vl[0], vl[1]);
                mma3(oacc[2 * np + 1], ah, al, vh[2], vh[3], vl[2], vl[3]);
            }
        }
        __syncthreads();     // all reads of K/V tiles done before next sts
    }

    // normalize + write out: attn_out[(b*N + n) * C + h*D + d]
    float inv0 = 1.f / l_run[0];
    float inv1 = 1.f / l_run[1];
    size_t orow0 = (size_t)(b * Nn + q0 + rq + g) * Cc + h * Dd;
    size_t orow1 = (size_t)(b * Nn + q0 + rq + 8 + g) * Cc + h * Dd;
    #pragma unroll
    for (int nt = 0; nt < 8; nt++) {
        int c = nt * 8 + 2 * t;
        *(float2*)&attn_out[orow0 + c] = make_float2(oacc[nt][0] * inv0, oacc[nt][1] * inv0);
        *(float2*)&attn_out[orow1 + c] = make_float2(oacc[nt][2] * inv1, oacc[nt][3] * inv1);
    }
}

// ---------------------------------------------------------------------------
// launch
// ---------------------------------------------------------------------------
extern "C" void kernel_launch(void* const* d_in, const int* in_sizes, int n_in,
                              void* d_out, int out_size)
{
    const float* x     = (const float*)d_in[0];
    const float* w_in  = (const float*)d_in[1];
    const float* b_in  = (const float*)d_in[2];
    const float* w_out = (const float*)d_in[3];
    const float* b_out = (const float*)d_in[4];
    float* out = (float*)d_out;

    float* qkv;
    float* attn;
    cudaGetSymbolAddress((void**)&qkv, g_qkv);
    cudaGetSymbolAddress((void**)&attn, g_attn);

    cudaFuncSetAttribute(gemm_bias_bf16x3, cudaFuncAttributeMaxDynamicSharedMemorySize,
                         (int)GEMM_SMEM);
    cudaFuncSetAttribute(flash_attn, cudaFuncAttributeMaxDynamicSharedMemorySize,
                         (int)FL_SMEM);

    const int M = Bb * Nn;  // 8192

    // 1) qkv = x @ w_in + b_in     (8192 x 3072 x 1024)
    gemm_bias_bf16x3<<<dim3(3 * Cc / BN, M / BM), 256, GEMM_SMEM>>>(
        x, w_in, b_in, qkv, M, 3 * Cc, Cc);

    // 2) flash attention -> attn (B,N,C)
    flash_attn<<<dim3(Bb * Hh, Nn / 128), 256, FL_SMEM>>>(qkv, attn);

    // 3) out = attn @ w_out + b_out   (8192 x 1024 x 1024)
    gemm_bias_bf16x3<<<dim3(Cc / BN, M / BM), 256, GEMM_SMEM>>>(
        attn, w_out, b_out, out, M, Cc, Cc);
}